// round 16
// baseline (speedup 1.0000x reference)
#include <cuda_runtime.h>
#include <cuda_fp16.h>
#include <math.h>
#include <stdint.h>

// ---------------------------------------------------------------- shapes
#define BB      64
#define CC      862
#define FBINS   257
#define DM      256
#define DFF     512
#define NL      3
#define EPSV    1e-5f

#define EMB_M   (BB*CC)                 // 55168
#define MROWS   (2*BB*CC)               // 110336
#define NSTATB  862
#define ROWS_PER_STATB 128              // 862*128 = 110336
#define KEMB    544                     // 514 padded to 17*32

// ---------------------------------------------------------------- scratch
__device__ float  g_act[(size_t)MROWS * DM];
__device__ float  g_src[(size_t)MROWS * DM];          // fp32 src (exact residual)
__device__ __half g_srch[(size_t)MROWS * DM];         // fp16 src (GEMM A / stats)
__device__ __half g_ffh[(size_t)MROWS * DFF];         // fp16 FF hidden
__device__ float  g_P  [(size_t)MROWS * DM];          // embed A-pack scratch
__device__ float  g_psum[DM * NSTATB];                // channel-major partials
__device__ float  g_psq [DM * NSTATB];
__device__ float  g_al[DM];
__device__ float  g_bt[DM];
__device__ __half g_w1h[DFF * DM];                    // W1 * BN1-affine, fp16
__device__ float  g_b1m[DFF];
__device__ __half g_w2h[NL * DM * DFF];               // W2 fp16 (all layers)
__device__ __half g_wEh[512 * KEMB];                  // embed B pack, fp16
__device__ float  g_bE[512];                          // embed bias pack

// ---------------------------------------------------------------- helpers
__device__ __forceinline__ uint32_t smem_u32(const void* p) {
    uint32_t a;
    asm("{ .reg .u64 t; cvta.to.shared.u64 t, %1; cvt.u32.u64 %0, t; }" : "=r"(a) : "l"(p));
    return a;
}

__device__ __forceinline__ void cp16(uint32_t dst, const void* src) {
    asm volatile("cp.async.cg.shared.global [%0], [%1], 16;" :: "r"(dst), "l"(src));
}
#define CP_COMMIT() asm volatile("cp.async.commit_group;" ::: "memory")
#define CP_WAIT1()  asm volatile("cp.async.wait_group 1;" ::: "memory")

__device__ __forceinline__ void ldsm4(uint32_t& r0, uint32_t& r1,
                                      uint32_t& r2, uint32_t& r3, uint32_t a) {
    asm volatile("ldmatrix.sync.aligned.m8n8.x4.shared.b16 {%0,%1,%2,%3}, [%4];"
        : "=r"(r0), "=r"(r1), "=r"(r2), "=r"(r3) : "r"(a));
}

// fp16 m16n8k16, fp32 accumulator
__device__ __forceinline__ void mma16(float* c,
    uint32_t a0, uint32_t a1, uint32_t a2, uint32_t a3,
    uint32_t b0, uint32_t b1)
{
    asm volatile(
        "mma.sync.aligned.m16n8k16.row.col.f32.f16.f16.f32 "
        "{%0,%1,%2,%3}, {%4,%5,%6,%7}, {%8,%9}, {%0,%1,%2,%3};"
        : "+f"(c[0]), "+f"(c[1]), "+f"(c[2]), "+f"(c[3])
        : "r"(a0), "r"(a1), "r"(a2), "r"(a3), "r"(b0), "r"(b1));
}

// fp16 m16n8k16, fp16 accumulator (ff1 only)
__device__ __forceinline__ void mma16h(uint32_t* c,
    uint32_t a0, uint32_t a1, uint32_t a2, uint32_t a3,
    uint32_t b0, uint32_t b1)
{
    asm volatile(
        "mma.sync.aligned.m16n8k16.row.col.f16.f16.f16.f16 "
        "{%0,%1}, {%2,%3,%4,%5}, {%6,%7}, {%0,%1};"
        : "+r"(c[0]), "+r"(c[1])
        : "r"(a0), "r"(a1), "r"(a2), "r"(a3), "r"(b0), "r"(b1));
}

__device__ __forceinline__ float gelu_exact(float h) {
    return 0.5f * h * (1.0f + erff(h * 0.70710678118654752f));
}

// ---------------------------------------------------------------- misc kernels
__global__ void k_init_affine() { g_al[threadIdx.x] = 1.0f; g_bt[threadIdx.x] = 0.0f; }

// ---------------- embed packing ----------------
__global__ void k_packA(const float* __restrict__ xre, const float* __restrict__ xim,
                        __half* __restrict__ Ah)
{
    size_t i = (size_t)blockIdx.x * 256 + threadIdx.x;
    if (i >= (size_t)EMB_M * KEMB) return;
    int k = (int)(i % KEMB);
    size_t m = i / KEMB;
    float v = 0.0f;
    if (k < FBINS)          v = xre[m * FBINS + k];
    else if (k < 2 * FBINS) v = xim[m * FBINS + (k - FBINS)];
    Ah[i] = __float2half_rn(v);
}

__global__ void k_packW(const float* __restrict__ Wre, const float* __restrict__ Wim)
{
    size_t i = (size_t)blockIdx.x * 256 + threadIdx.x;
    if (i >= (size_t)512 * KEMB) return;
    int k = (int)(i % KEMB);
    int n = (int)(i / KEMB);
    float v = 0.0f;
    if (n < 256) {         // which = 0: [Wre | -Wim]
        if (k < FBINS)          v = Wre[n * FBINS + k];
        else if (k < 2 * FBINS) v = -Wim[n * FBINS + (k - FBINS)];
    } else {               // which = 1: [Wim | Wre]
        int nn = n - 256;
        if (k < FBINS)          v = Wim[nn * FBINS + k];
        else if (k < 2 * FBINS) v = Wre[nn * FBINS + (k - FBINS)];
    }
    g_wEh[i] = __float2half_rn(v);
}

__global__ void k_packBias(const float* __restrict__ bre, const float* __restrict__ bim)
{
    int t = threadIdx.x;    // 512
    g_bE[t] = (t < 256) ? bre[t] : bim[t - 256];
}

// ---------------- FUSED attention: gather -> transpose tile -> residual ----
__global__ __launch_bounds__(256) void k_attn(
    const float* __restrict__ act, float* __restrict__ src,
    __half* __restrict__ srch)
{
    __shared__ float sre[32][33];
    __shared__ float sim[32][33];
    const int c0 = blockIdx.x * 32;
    const int d0 = blockIdx.y * 32;
    const int b  = blockIdx.z;
    const int tx = threadIdx.x & 31;
    const int ty = threadIdx.x >> 5;

    {
        const int d2 = d0 + tx;
        const int d3 = (DM - 1) - d2;
        const float al2 = g_al[d2], bt2 = g_bt[d2];
        const float al3 = g_al[d3], bt3 = g_bt[d3];

        #pragma unroll
        for (int rr = 0; rr < 4; rr++) {
            int c2l = ty + rr * 8;
            int c2 = c0 + c2l;
            if (c2 < CC) {
                int c3 = (CC - 1) - c2;
                float qr = act[((size_t)b        * CC + c2) * DM + d2] * al2 + bt2;
                float qi = act[((size_t)(64 + b) * CC + c2) * DM + d2] * al2 + bt2;
                float kr = act[((size_t)b        * CC + c3) * DM + d3] * al3 + bt3;
                float ki = act[((size_t)(64 + b) * CC + c3) * DM + d3] * al3 + bt3;
                float asr = qr * kr - qi * ki;
                float asi = qr * ki - qi * kr;
                sre[c2l][tx] = 0.25f * (asr - asi) * qr;
                sim[c2l][tx] = 0.25f * (asr + asi) * qr;
            }
        }
    }
    __syncthreads();

    const int c2 = c0 + tx;
    if (c2 < CC) {
        #pragma unroll
        for (int rr = 0; rr < 4; rr++) {
            int d2l = ty + rr * 8;
            int t = (d0 + d2l) * CC + c2;
            int d = t & 255;
            float al = g_al[d], bt = g_bt[d];
            size_t e0 = (size_t)b * (CC * DM) + t;
            size_t e1 = e0 + (size_t)EMB_M * DM;
            float y0 = act[e0] * al + bt + sre[tx][d2l];
            float y1 = act[e1] * al + bt + sim[tx][d2l];
            src[e0] = y0;
            src[e1] = y1;
            srch[e0] = __float2half_rn(y0);
            srch[e1] = __float2half_rn(y1);
        }
    }
}

// partials are CHANNEL-MAJOR: g_psum[ch*NSTATB + blk]; fp16 input (BN1)
__global__ void k_stats_h(const __half* __restrict__ buf)
{
    int ch = threadIdx.x;
    int blk = blockIdx.x;
    float s = 0.0f, q = 0.0f;
    size_t row0 = (size_t)blk * ROWS_PER_STATB;
    #pragma unroll 16
    for (int i = 0; i < ROWS_PER_STATB; i++) {
        float v = __half2float(buf[(row0 + i) * DM + ch]);
        s += v; q += v * v;
    }
    g_psum[(size_t)ch * NSTATB + blk] = s;
    g_psq [(size_t)ch * NSTATB + blk] = q;
}

// one block per channel: coalesced contiguous reads, smem tree-reduce
__global__ __launch_bounds__(256) void k_finalize(
    const float* __restrict__ gamma, const float* __restrict__ beta)
{
    __shared__ float ss[256], qq[256];
    int ch = blockIdx.x;
    int t = threadIdx.x;
    float s = 0.0f, q = 0.0f;
    for (int i = t; i < NSTATB; i += 256) {
        s += g_psum[(size_t)ch * NSTATB + i];
        q += g_psq [(size_t)ch * NSTATB + i];
    }
    ss[t] = s; qq[t] = q;
    __syncthreads();
    #pragma unroll
    for (int st = 128; st > 0; st >>= 1) {
        if (t < st) { ss[t] += ss[t + st]; qq[t] += qq[t + st]; }
        __syncthreads();
    }
    if (t == 0) {
        const float inv = 1.0f / (float)MROWS;
        float m = ss[0] * inv;
        float v = qq[0] * inv - m * m;
        float al = gamma[ch] * rsqrtf(v + EPSV);
        g_al[ch] = al;
        g_bt[ch] = beta[ch] - m * al;
    }
}

// fold BN1 affine into W1/b1; store W1' in fp16
__global__ __launch_bounds__(256) void k_fold(const float* __restrict__ W1,
                                              const float* __restrict__ b1)
{
    __shared__ float red[256];
    int f = blockIdx.x;
    int t = threadIdx.x;
    float w = W1[(size_t)f * DM + t];
    g_w1h[(size_t)f * DM + t] = __float2half_rn(w * g_al[t]);
    red[t] = w * g_bt[t];
    __syncthreads();
    #pragma unroll
    for (int s = 128; s > 0; s >>= 1) {
        if (t < s) red[t] += red[t + s];
        __syncthreads();
    }
    if (t == 0) g_b1m[f] = b1[f] + red[0];
}

// fp16-convert all W2 layers once
__global__ void k_roundW2(const float* __restrict__ W2)
{
    int i = blockIdx.x * 256 + threadIdx.x;   // NL*DM*DFF
    g_w2h[i] = __float2half_rn(W2[i]);
}

__global__ void k_out(const float* __restrict__ act, float* __restrict__ out)
{
    size_t e = (size_t)blockIdx.x * blockDim.x + threadIdx.x;
    if (e >= (size_t)BB * CC * DM) return;
    int d = (int)(e & 255);
    size_t r = e >> 8;
    float al = g_al[d], bt = g_bt[d];
    float v0 = act[r * DM + d] * al + bt;
    float v1 = act[((size_t)EMB_M + r) * DM + d] * al + bt;
    *(float2*)&out[2 * e] = make_float2(v0, v1);
}

// ---------------------------------------------------------------- unified fp16 GEMM
// MODE 0: ff1  : ffh[M,512] = fp16(gelu( srch[M,256] @ w1h^T + b1m ))  [fp16 acc]
// MODE 1: ff2  : act[M,256] = ffh[M,512] @ w2h^T + b2 + (src*al+bt)   [fp32 acc]
//                + FUSED BN2 column-stats via smem staging
// MODE 2: embed: act[which][M,256] = Ah[M,544] @ wEh^T + bE           [fp32 acc]
// CTA tile 128x128, 128 threads = 4 warps (2M x 2N), warp tile 64x64.
// BK=32 fp16, 3-stage cp.async pipeline, 80-byte padded rows.
#define RSH     40                        // row stride in halves (80 bytes)
#define STG     3
#define CHUNK_H (128 * RSH)               // halves per tile per stage
#define CHUNK_B (CHUNK_H * 2)             // bytes per tile per stage (10240)
#define DYNSM   (STG * CHUNK_B * 2)       // A + B rings = 61440 bytes

template<int MODE>
__global__ __launch_bounds__(128, 3) void k_ffgemm(
    const __half* __restrict__ A,  const __half* __restrict__ Bm,
    const float* __restrict__ bias, const float* __restrict__ src,
    float* __restrict__ outf, __half* __restrict__ outh)
{
    constexpr int KK   = (MODE == 0) ? DM : (MODE == 1) ? DFF : KEMB;
    constexpr int NKB  = KK / 32;
    constexpr int ASTR = KK;
    constexpr int OSTR = (MODE == 0) ? DFF : DM;
    constexpr bool HACC = (MODE == 0);

    extern __shared__ __half dynh[];
    __half* pA = dynh;                     // [STG][128][RSH]
    __half* pB = dynh + STG * CHUNK_H;

    const int tid  = threadIdx.x;
    const int lane = tid & 31;
    const int w    = tid >> 5;
    const int wm   = w & 1;      // 0..1  (M)
    const int wn   = w >> 1;     // 0..1  (N)
    const int m0   = blockIdx.y * 128;
    const int n0   = blockIdx.x * 128;
    const int g    = lane >> 2;  // 0..7
    const int tg   = lane & 3;   // 0..3

    const uint32_t baseA = smem_u32(pA);
    const uint32_t baseB = smem_u32(pB);

    // ldmatrix per-lane offsets (bytes) within a chunk tile
    const int lr = lane & 7;
    const int b3 = (lane >> 3) & 1;
    const int b4 = (lane >> 4) & 1;
    uint32_t offA[4], offB[4];
    #pragma unroll
    for (int mt = 0; mt < 4; mt++) {
        int row = wm * 64 + mt * 16 + lr + b3 * 8;
        offA[mt] = (uint32_t)(row * (RSH * 2) + b4 * 16);
    }
    #pragma unroll
    for (int ntp = 0; ntp < 4; ntp++) {
        int row = wn * 64 + ntp * 16 + lr + b4 * 8;
        offB[ntp] = (uint32_t)(row * (RSH * 2) + b3 * 16);
    }

    float    acc [HACC ? 1 : 4][8][4];   // fp32 acc (MODE 1/2)
    uint32_t acch[HACC ? 4 : 1][8][2];   // fp16 acc (MODE 0)
    if (HACC) {
        #pragma unroll
        for (int mt = 0; mt < 4; mt++)
            #pragma unroll
            for (int nt = 0; nt < 8; nt++) { acch[mt][nt][0] = 0u; acch[mt][nt][1] = 0u; }
    } else {
        #pragma unroll
        for (int mt = 0; mt < 4; mt++)
            #pragma unroll
            for (int nt = 0; nt < 8; nt++)
                #pragma unroll
                for (int i = 0; i < 4; i++) acc[mt][nt][i] = 0.0f;
    }

    const int srow = tid >> 2, skq = tid & 3;

    auto issue = [&](int kb, int s) {
        uint32_t dA = baseA + (uint32_t)s * CHUNK_B;
        uint32_t dB = baseB + (uint32_t)s * CHUNK_B;
        #pragma unroll
        for (int it = 0; it < 4; it++) {
            int row = it * 32 + srow;
            int kg  = kb * 32 + skq * 8;   // halves
            cp16(dA + row * (RSH * 2) + skq * 16, &A [(size_t)(m0 + row) * ASTR + kg]);
            cp16(dB + row * (RSH * 2) + skq * 16, &Bm[(size_t)(n0 + row) * ASTR + kg]);
        }
    };

    auto compute = [&](int s) {
        uint32_t cA = baseA + (uint32_t)s * CHUNK_B;
        uint32_t cB = baseB + (uint32_t)s * CHUNK_B;
        #pragma unroll
        for (int p = 0; p < 2; p++) {
            uint32_t af[4][4];
            #pragma unroll
            for (int mt = 0; mt < 4; mt++)
                ldsm4(af[mt][0], af[mt][1], af[mt][2], af[mt][3],
                      cA + offA[mt] + p * 32);
            uint32_t bf[8][2];
            #pragma unroll
            for (int ntp = 0; ntp < 4; ntp++)
                ldsm4(bf[2 * ntp][0], bf[2 * ntp][1],
                      bf[2 * ntp + 1][0], bf[2 * ntp + 1][1],
                      cB + offB[ntp] + p * 32);
            #pragma unroll
            for (int mt = 0; mt < 4; mt++)
                #pragma unroll
                for (int nt = 0; nt < 8; nt++) {
                    if (HACC)
                        mma16h(acch[mt][nt], af[mt][0], af[mt][1], af[mt][2], af[mt][3],
                               bf[nt][0], bf[nt][1]);
                    else
                        mma16(acc[mt][nt], af[mt][0], af[mt][1], af[mt][2], af[mt][3],
                              bf[nt][0], bf[nt][1]);
                }
        }
    };

    issue(0, 0); CP_COMMIT();
    issue(1, 1); CP_COMMIT();

    #pragma unroll 1
    for (int kb = 0; kb < NKB; kb++) {
        CP_WAIT1();                 // group kb complete (only kb+1 may be pending)
        __syncthreads();            // data visible; stage (kb+2)%3 free to refill
        if (kb + 2 < NKB) issue(kb + 2, (kb + 2) % 3);
        CP_COMMIT();
        compute(kb % 3);
    }

    // ---- epilogue
    const int whichv = (MODE == 2) ? (n0 >> 8) : 0;
    float* outfp = (MODE == 2) ? (outf + (size_t)whichv * EMB_M * DM) : outf;
    const int ncorr = (MODE == 2) ? whichv * 256 : 0;

    // MODE 1: stage outputs in smem (fp16) for fused BN2 column stats.
    if (MODE == 1) __syncthreads();

    #pragma unroll
    for (int mt = 0; mt < 4; mt++) {
        int r0 = m0 + wm * 64 + mt * 16 + g;
        int r1 = r0 + 8;
        #pragma unroll
        for (int nt = 0; nt < 8; nt++) {
            int cb = n0 + wn * 64 + nt * 8 + tg * 2;
            float2 bi = *(const float2*)&bias[cb];
            if (MODE == 0) {
                float2 f0 = __half22float2(*(__half2*)&acch[mt][nt][0]);
                float2 f1 = __half22float2(*(__half2*)&acch[mt][nt][1]);
                __half2 h0 = __floats2half2_rn(gelu_exact(f0.x + bi.x),
                                               gelu_exact(f0.y + bi.y));
                __half2 h1 = __floats2half2_rn(gelu_exact(f1.x + bi.x),
                                               gelu_exact(f1.y + bi.y));
                *(__half2*)&outh[(size_t)r0 * OSTR + cb] = h0;
                *(__half2*)&outh[(size_t)r1 * OSTR + cb] = h1;
            } else if (MODE == 1) {
                float* c = acc[mt][nt];
                float2 al = *(const float2*)&g_al[cb];
                float2 bt = *(const float2*)&g_bt[cb];
                float2 s0 = *(const float2*)&src[(size_t)r0 * DM + cb];
                float2 s1 = *(const float2*)&src[(size_t)r1 * DM + cb];
                float2 o0 = make_float2(c[0] + bi.x + s0.x * al.x + bt.x,
                                        c[1] + bi.y + s0.y * al.y + bt.y);
                float2 o1 = make_float2(c[2] + bi.x + s1.x * al.x + bt.x,
                                        c[3] + bi.y + s1.y * al.y + bt.y);
                *(float2*)&outf[(size_t)r0 * OSTR + cb] = o0;
                *(float2*)&outf[(size_t)r1 * OSTR + cb] = o1;
                int rl0 = wm * 64 + mt * 16 + g;      // local rows
                int cl  = wn * 64 + nt * 8 + tg * 2;  // local cols
                *(__half2*)&dynh[rl0 * 128 + cl]       = __floats2half2_rn(o0.x, o0.y);
                *(__half2*)&dynh[(rl0 + 8) * 128 + cl] = __floats2half2_rn(o1.x, o1.y);
            } else {
                float* c = acc[mt][nt];
                int cl = cb - ncorr;
                float2 o0 = make_float2(c[0] + bi.x, c[1] + bi.y);
                float2 o1 = make_float2(c[2] + bi.x, c[3] + bi.y);
                *(float2*)&outfp[(size_t)r0 * OSTR + cl] = o0;
                *(float2*)&outfp[(size_t)r1 * OSTR + cl] = o1;
            }
        }
    }

    if (MODE == 1) {
        __syncthreads();
        // each thread reduces one column of the 128x128 staged tile
        float s = 0.0f, q = 0.0f;
        #pragma unroll 8
        for (int r = 0; r < 128; r++) {
            float v = __half2float(dynh[r * 128 + tid]);
            s += v; q += v * v;
        }
        g_psum[(size_t)(n0 + tid) * NSTATB + blockIdx.y] = s;
        g_psq [(size_t)(n0 + tid) * NSTATB + blockIdx.y] = q;
    }
}

// ---------------------------------------------------------------- launch
extern "C" void kernel_launch(void* const* d_in, const int* in_sizes, int n_in,
                              void* d_out, int out_size)
{
    const float* x_re   = (const float*)d_in[0];
    const float* x_im   = (const float*)d_in[1];
    const float* embWre = (const float*)d_in[2];
    const float* embWim = (const float*)d_in[3];
    const float* embbre = (const float*)d_in[4];
    const float* embbim = (const float*)d_in[5];
    const float* W1     = (const float*)d_in[6];
    const float* b1     = (const float*)d_in[7];
    const float* W2     = (const float*)d_in[8];
    const float* b2     = (const float*)d_in[9];
    const float* gamma1 = (const float*)d_in[10];
    const float* beta1  = (const float*)d_in[11];
    const float* gamma2 = (const float*)d_in[12];
    const float* beta2  = (const float*)d_in[13];
    float* out = (float*)d_out;

    float*  act  = nullptr; float*  src = nullptr; __half* srch = nullptr;
    __half* ffh  = nullptr; float*  P   = nullptr;
    __half* w1h  = nullptr; float*  b1m = nullptr; __half* w2h  = nullptr;
    __half* wEh  = nullptr; float*  bE  = nullptr;
    cudaGetSymbolAddress((void**)&act,  g_act);
    cudaGetSymbolAddress((void**)&src,  g_src);
    cudaGetSymbolAddress((void**)&srch, g_srch);
    cudaGetSymbolAddress((void**)&ffh,  g_ffh);
    cudaGetSymbolAddress((void**)&P,    g_P);
    cudaGetSymbolAddress((void**)&w1h,  g_w1h);
    cudaGetSymbolAddress((void**)&b1m,  g_b1m);
    cudaGetSymbolAddress((void**)&w2h,  g_w2h);
    cudaGetSymbolAddress((void**)&wEh,  g_wEh);
    cudaGetSymbolAddress((void**)&bE,   g_bE);

    cudaFuncSetAttribute(k_ffgemm<0>, cudaFuncAttributeMaxDynamicSharedMemorySize, DYNSM);
    cudaFuncSetAttribute(k_ffgemm<1>, cudaFuncAttributeMaxDynamicSharedMemorySize, DYNSM);
    cudaFuncSetAttribute(k_ffgemm<2>, cudaFuncAttributeMaxDynamicSharedMemorySize, DYNSM);

    k_init_affine<<<1, DM>>>();
    k_roundW2<<<(NL * DM * DFF) / 256, 256>>>(W2);

    // embed: pack fp16 operands, then fp16 GEMM
    __half* Ah = (__half*)P;   // reuse g_P (embed runs before any attn)
    {
        size_t na = (size_t)EMB_M * KEMB;
        k_packA<<<(int)((na + 255) / 256), 256>>>(x_re, x_im, Ah);
        size_t nb = (size_t)512 * KEMB;
        k_packW<<<(int)((nb + 255) / 256), 256>>>(embWre, embWim);
        k_packBias<<<1, 512>>>(embbre, embbim);
        dim3 ge(512 / 128, EMB_M / 128);
        k_ffgemm<2><<<ge, 128, DYNSM>>>(Ah, wEh, bE, nullptr, act, nullptr);
    }

    for (int l = 0; l < NL; l++) {
        const float* W1l = W1 + (size_t)l * DFF * DM;
        const float* b1l = b1 + (size_t)l * DFF;
        const float* b2l = b2 + (size_t)l * DM;
        __half* w2hl = w2h + (size_t)l * DM * DFF;

        {
            dim3 ga((CC + 31) / 32, DM / 32, BB);
            k_attn<<<ga, 256>>>(act, src, srch);
        }

        k_stats_h<<<NSTATB, DM>>>(srch);
        k_finalize<<<DM, 256>>>(gamma1 + l * DM, beta1 + l * DM);
        k_fold<<<DFF, DM>>>(W1l, b1l);

        {
            dim3 g1(DFF / 128, MROWS / 128);
            k_ffgemm<0><<<g1, 128, DYNSM>>>(srch, w1h, b1m, nullptr, nullptr, ffh);
            dim3 g2(DM / 128, MROWS / 128);
            k_ffgemm<1><<<g2, 128, DYNSM>>>(ffh, w2hl, b2l, src, act, nullptr);
        }

        // BN2 stats produced by ff2's fused smem-staged epilogue
        k_finalize<<<DM, 256>>>(gamma2 + l * DM, beta2 + l * DM);
    }

    const size_t NO = (size_t)BB * CC * DM;
    k_out<<<(int)((NO + 255) / 256), 256>>>(act, out);
}

// round 17
// speedup vs baseline: 1.4116x; 1.4116x over previous
#include <cuda_runtime.h>
#include <cuda_fp16.h>
#include <math.h>
#include <stdint.h>

// ---------------------------------------------------------------- shapes
#define BB      64
#define CC      862
#define FBINS   257
#define DM      256
#define DFF     512
#define NL      3
#define EPSV    1e-5f

#define EMB_M   (BB*CC)                 // 55168
#define MROWS   (2*BB*CC)               // 110336
#define NSTATB  862
#define ROWS_PER_STATB 128              // 862*128 = 110336
#define KEMB    544                     // 514 padded to 17*32

// ---------------------------------------------------------------- scratch
__device__ float  g_act[(size_t)MROWS * DM];
__device__ float  g_src[(size_t)MROWS * DM];          // fp32 src (exact residual)
__device__ __half g_srch[(size_t)MROWS * DM];         // fp16 src (GEMM A / stats)
__device__ __half g_ffh[(size_t)MROWS * DFF];         // fp16 FF hidden
__device__ float  g_P  [(size_t)MROWS * DM];          // embed A-pack scratch
__device__ float  g_psum[DM * NSTATB];                // channel-major partials
__device__ float  g_psq [DM * NSTATB];
__device__ float  g_al[DM];
__device__ float  g_bt[DM];
__device__ __half g_w1h[DFF * DM];                    // W1 * BN1-affine, fp16
__device__ float  g_b1m[DFF];
__device__ __half g_w2h[NL * DM * DFF];               // W2 fp16 (all layers)
__device__ __half g_wEh[512 * KEMB];                  // embed B pack, fp16
__device__ float  g_bE[512];                          // embed bias pack

// ---------------------------------------------------------------- helpers
__device__ __forceinline__ uint32_t smem_u32(const void* p) {
    uint32_t a;
    asm("{ .reg .u64 t; cvta.to.shared.u64 t, %1; cvt.u32.u64 %0, t; }" : "=r"(a) : "l"(p));
    return a;
}

__device__ __forceinline__ void cp16(uint32_t dst, const void* src) {
    asm volatile("cp.async.cg.shared.global [%0], [%1], 16;" :: "r"(dst), "l"(src));
}
#define CP_COMMIT() asm volatile("cp.async.commit_group;" ::: "memory")
#define CP_WAIT1()  asm volatile("cp.async.wait_group 1;" ::: "memory")

__device__ __forceinline__ void ldsm4(uint32_t& r0, uint32_t& r1,
                                      uint32_t& r2, uint32_t& r3, uint32_t a) {
    asm volatile("ldmatrix.sync.aligned.m8n8.x4.shared.b16 {%0,%1,%2,%3}, [%4];"
        : "=r"(r0), "=r"(r1), "=r"(r2), "=r"(r3) : "r"(a));
}

// fp16 m16n8k16, fp32 accumulator
__device__ __forceinline__ void mma16(float* c,
    uint32_t a0, uint32_t a1, uint32_t a2, uint32_t a3,
    uint32_t b0, uint32_t b1)
{
    asm volatile(
        "mma.sync.aligned.m16n8k16.row.col.f32.f16.f16.f32 "
        "{%0,%1,%2,%3}, {%4,%5,%6,%7}, {%8,%9}, {%0,%1,%2,%3};"
        : "+f"(c[0]), "+f"(c[1]), "+f"(c[2]), "+f"(c[3])
        : "r"(a0), "r"(a1), "r"(a2), "r"(a3), "r"(b0), "r"(b1));
}

__device__ __forceinline__ float gelu_exact(float h) {
    return 0.5f * h * (1.0f + erff(h * 0.70710678118654752f));
}

// ---------------------------------------------------------------- misc kernels
__global__ void k_init_affine() { g_al[threadIdx.x] = 1.0f; g_bt[threadIdx.x] = 0.0f; }

// ---------------- embed packing ----------------
__global__ void k_packA(const float* __restrict__ xre, const float* __restrict__ xim,
                        __half* __restrict__ Ah)
{
    size_t i = (size_t)blockIdx.x * 256 + threadIdx.x;
    if (i >= (size_t)EMB_M * KEMB) return;
    int k = (int)(i % KEMB);
    size_t m = i / KEMB;
    float v = 0.0f;
    if (k < FBINS)          v = xre[m * FBINS + k];
    else if (k < 2 * FBINS) v = xim[m * FBINS + (k - FBINS)];
    Ah[i] = __float2half_rn(v);
}

__global__ void k_packW(const float* __restrict__ Wre, const float* __restrict__ Wim)
{
    size_t i = (size_t)blockIdx.x * 256 + threadIdx.x;
    if (i >= (size_t)512 * KEMB) return;
    int k = (int)(i % KEMB);
    int n = (int)(i / KEMB);
    float v = 0.0f;
    if (n < 256) {         // which = 0: [Wre | -Wim]
        if (k < FBINS)          v = Wre[n * FBINS + k];
        else if (k < 2 * FBINS) v = -Wim[n * FBINS + (k - FBINS)];
    } else {               // which = 1: [Wim | Wre]
        int nn = n - 256;
        if (k < FBINS)          v = Wim[nn * FBINS + k];
        else if (k < 2 * FBINS) v = Wre[nn * FBINS + (k - FBINS)];
    }
    g_wEh[i] = __float2half_rn(v);
}

__global__ void k_packBias(const float* __restrict__ bre, const float* __restrict__ bim)
{
    int t = threadIdx.x;    // 512
    g_bE[t] = (t < 256) ? bre[t] : bim[t - 256];
}

// ---------------- FUSED attention: gather -> transpose tile -> residual ----
__global__ __launch_bounds__(256) void k_attn(
    const float* __restrict__ act, float* __restrict__ src,
    __half* __restrict__ srch)
{
    __shared__ float sre[32][33];
    __shared__ float sim[32][33];
    const int c0 = blockIdx.x * 32;
    const int d0 = blockIdx.y * 32;
    const int b  = blockIdx.z;
    const int tx = threadIdx.x & 31;
    const int ty = threadIdx.x >> 5;

    {
        const int d2 = d0 + tx;
        const int d3 = (DM - 1) - d2;
        const float al2 = g_al[d2], bt2 = g_bt[d2];
        const float al3 = g_al[d3], bt3 = g_bt[d3];

        #pragma unroll
        for (int rr = 0; rr < 4; rr++) {
            int c2l = ty + rr * 8;
            int c2 = c0 + c2l;
            if (c2 < CC) {
                int c3 = (CC - 1) - c2;
                float qr = act[((size_t)b        * CC + c2) * DM + d2] * al2 + bt2;
                float qi = act[((size_t)(64 + b) * CC + c2) * DM + d2] * al2 + bt2;
                float kr = act[((size_t)b        * CC + c3) * DM + d3] * al3 + bt3;
                float ki = act[((size_t)(64 + b) * CC + c3) * DM + d3] * al3 + bt3;
                float asr = qr * kr - qi * ki;
                float asi = qr * ki - qi * kr;
                sre[c2l][tx] = 0.25f * (asr - asi) * qr;
                sim[c2l][tx] = 0.25f * (asr + asi) * qr;
            }
        }
    }
    __syncthreads();

    const int c2 = c0 + tx;
    if (c2 < CC) {
        #pragma unroll
        for (int rr = 0; rr < 4; rr++) {
            int d2l = ty + rr * 8;
            int t = (d0 + d2l) * CC + c2;
            int d = t & 255;
            float al = g_al[d], bt = g_bt[d];
            size_t e0 = (size_t)b * (CC * DM) + t;
            size_t e1 = e0 + (size_t)EMB_M * DM;
            float y0 = act[e0] * al + bt + sre[tx][d2l];
            float y1 = act[e1] * al + bt + sim[tx][d2l];
            src[e0] = y0;
            src[e1] = y1;
            srch[e0] = __float2half_rn(y0);
            srch[e1] = __float2half_rn(y1);
        }
    }
}

// partials are CHANNEL-MAJOR: g_psum[ch*NSTATB + blk]; fp16 input (BN1)
__global__ void k_stats_h(const __half* __restrict__ buf)
{
    int ch = threadIdx.x;
    int blk = blockIdx.x;
    float s = 0.0f, q = 0.0f;
    size_t row0 = (size_t)blk * ROWS_PER_STATB;
    #pragma unroll 16
    for (int i = 0; i < ROWS_PER_STATB; i++) {
        float v = __half2float(buf[(row0 + i) * DM + ch]);
        s += v; q += v * v;
    }
    g_psum[(size_t)ch * NSTATB + blk] = s;
    g_psq [(size_t)ch * NSTATB + blk] = q;
}

// one block per channel: coalesced contiguous reads, smem tree-reduce
__global__ __launch_bounds__(256) void k_finalize(
    const float* __restrict__ gamma, const float* __restrict__ beta)
{
    __shared__ float ss[256], qq[256];
    int ch = blockIdx.x;
    int t = threadIdx.x;
    float s = 0.0f, q = 0.0f;
    for (int i = t; i < NSTATB; i += 256) {
        s += g_psum[(size_t)ch * NSTATB + i];
        q += g_psq [(size_t)ch * NSTATB + i];
    }
    ss[t] = s; qq[t] = q;
    __syncthreads();
    #pragma unroll
    for (int st = 128; st > 0; st >>= 1) {
        if (t < st) { ss[t] += ss[t + st]; qq[t] += qq[t + st]; }
        __syncthreads();
    }
    if (t == 0) {
        const float inv = 1.0f / (float)MROWS;
        float m = ss[0] * inv;
        float v = qq[0] * inv - m * m;
        float al = gamma[ch] * rsqrtf(v + EPSV);
        g_al[ch] = al;
        g_bt[ch] = beta[ch] - m * al;
    }
}

// fold BN1 affine into W1/b1; store W1' in fp16
__global__ __launch_bounds__(256) void k_fold(const float* __restrict__ W1,
                                              const float* __restrict__ b1)
{
    __shared__ float red[256];
    int f = blockIdx.x;
    int t = threadIdx.x;
    float w = W1[(size_t)f * DM + t];
    g_w1h[(size_t)f * DM + t] = __float2half_rn(w * g_al[t]);
    red[t] = w * g_bt[t];
    __syncthreads();
    #pragma unroll
    for (int s = 128; s > 0; s >>= 1) {
        if (t < s) red[t] += red[t + s];
        __syncthreads();
    }
    if (t == 0) g_b1m[f] = b1[f] + red[0];
}

// fp16-convert all W2 layers once
__global__ void k_roundW2(const float* __restrict__ W2)
{
    int i = blockIdx.x * 256 + threadIdx.x;   // NL*DM*DFF
    g_w2h[i] = __float2half_rn(W2[i]);
}

__global__ void k_out(const float* __restrict__ act, float* __restrict__ out)
{
    size_t e = (size_t)blockIdx.x * blockDim.x + threadIdx.x;
    if (e >= (size_t)BB * CC * DM) return;
    int d = (int)(e & 255);
    size_t r = e >> 8;
    float al = g_al[d], bt = g_bt[d];
    float v0 = act[r * DM + d] * al + bt;
    float v1 = act[((size_t)EMB_M + r) * DM + d] * al + bt;
    *(float2*)&out[2 * e] = make_float2(v0, v1);
}

// ---------------------------------------------------------------- unified fp16 GEMM
// MODE 0: ff1  : ffh[M,512] = fp16(gelu( srch[M,256] @ w1h^T + b1m ))
// MODE 1: ff2  : act[M,256] = ffh[M,512] @ w2h^T + b2 + (src*al+bt)   [src fp32]
//                + FUSED BN2 column-stats via smem staging (low reg cost)
// MODE 2: embed: act[which][M,256] = Ah[M,544] @ wEh^T + bE  (which = n0>>8)
// CTA tile 128x128, 128 threads = 4 warps (2M x 2N), warp tile 64x64.
// BK=32 fp16, 3-stage cp.async pipeline, 80-byte padded rows.
#define RSH     40                        // row stride in halves (80 bytes)
#define STG     3
#define CHUNK_H (128 * RSH)               // halves per tile per stage
#define CHUNK_B (CHUNK_H * 2)             // bytes per tile per stage (10240)
#define DYNSM   (STG * CHUNK_B * 2)       // A + B rings = 61440 bytes

template<int MODE>
__global__ __launch_bounds__(128, 3) void k_ffgemm(
    const __half* __restrict__ A,  const __half* __restrict__ Bm,
    const float* __restrict__ bias, const float* __restrict__ src,
    float* __restrict__ outf, __half* __restrict__ outh)
{
    constexpr int KK   = (MODE == 0) ? DM : (MODE == 1) ? DFF : KEMB;
    constexpr int NKB  = KK / 32;
    constexpr int ASTR = KK;
    constexpr int OSTR = (MODE == 0) ? DFF : DM;

    extern __shared__ __half dynh[];
    __half* pA = dynh;                     // [STG][128][RSH]
    __half* pB = dynh + STG * CHUNK_H;

    const int tid  = threadIdx.x;
    const int lane = tid & 31;
    const int w    = tid >> 5;
    const int wm   = w & 1;      // 0..1  (M)
    const int wn   = w >> 1;     // 0..1  (N)
    const int m0   = blockIdx.y * 128;
    const int n0   = blockIdx.x * 128;
    const int g    = lane >> 2;  // 0..7
    const int tg   = lane & 3;   // 0..3

    const uint32_t baseA = smem_u32(pA);
    const uint32_t baseB = smem_u32(pB);

    // ldmatrix per-lane offsets (bytes) within a chunk tile
    const int lr = lane & 7;
    const int b3 = (lane >> 3) & 1;
    const int b4 = (lane >> 4) & 1;
    uint32_t offA[4], offB[4];
    #pragma unroll
    for (int mt = 0; mt < 4; mt++) {
        int row = wm * 64 + mt * 16 + lr + b3 * 8;
        offA[mt] = (uint32_t)(row * (RSH * 2) + b4 * 16);
    }
    #pragma unroll
    for (int ntp = 0; ntp < 4; ntp++) {
        int row = wn * 64 + ntp * 16 + lr + b4 * 8;
        offB[ntp] = (uint32_t)(row * (RSH * 2) + b3 * 16);
    }

    float acc[4][8][4];
    #pragma unroll
    for (int mt = 0; mt < 4; mt++)
        #pragma unroll
        for (int nt = 0; nt < 8; nt++)
            #pragma unroll
            for (int i = 0; i < 4; i++) acc[mt][nt][i] = 0.0f;

    const int srow = tid >> 2, skq = tid & 3;

    auto issue = [&](int kb, int s) {
        uint32_t dA = baseA + (uint32_t)s * CHUNK_B;
        uint32_t dB = baseB + (uint32_t)s * CHUNK_B;
        #pragma unroll
        for (int it = 0; it < 4; it++) {
            int row = it * 32 + srow;
            int kg  = kb * 32 + skq * 8;   // halves
            cp16(dA + row * (RSH * 2) + skq * 16, &A [(size_t)(m0 + row) * ASTR + kg]);
            cp16(dB + row * (RSH * 2) + skq * 16, &Bm[(size_t)(n0 + row) * ASTR + kg]);
        }
    };

    auto compute = [&](int s) {
        uint32_t cA = baseA + (uint32_t)s * CHUNK_B;
        uint32_t cB = baseB + (uint32_t)s * CHUNK_B;
        #pragma unroll
        for (int p = 0; p < 2; p++) {
            uint32_t af[4][4];
            #pragma unroll
            for (int mt = 0; mt < 4; mt++)
                ldsm4(af[mt][0], af[mt][1], af[mt][2], af[mt][3],
                      cA + offA[mt] + p * 32);
            uint32_t bf[8][2];
            #pragma unroll
            for (int ntp = 0; ntp < 4; ntp++)
                ldsm4(bf[2 * ntp][0], bf[2 * ntp][1],
                      bf[2 * ntp + 1][0], bf[2 * ntp + 1][1],
                      cB + offB[ntp] + p * 32);
            #pragma unroll
            for (int mt = 0; mt < 4; mt++)
                #pragma unroll
                for (int nt = 0; nt < 8; nt++)
                    mma16(acc[mt][nt], af[mt][0], af[mt][1], af[mt][2], af[mt][3],
                          bf[nt][0], bf[nt][1]);
        }
    };

    issue(0, 0); CP_COMMIT();
    issue(1, 1); CP_COMMIT();

    #pragma unroll 1
    for (int kb = 0; kb < NKB; kb++) {
        CP_WAIT1();                 // group kb complete (only kb+1 may be pending)
        __syncthreads();            // data visible; stage (kb+2)%3 free to refill
        if (kb + 2 < NKB) issue(kb + 2, (kb + 2) % 3);
        CP_COMMIT();
        compute(kb % 3);
    }

    // ---- epilogue
    const int whichv = (MODE == 2) ? (n0 >> 8) : 0;
    float* outfp = (MODE == 2) ? (outf + (size_t)whichv * EMB_M * DM) : outf;
    const int ncorr = (MODE == 2) ? whichv * 256 : 0;

    // MODE 1: stage outputs in smem (fp16) for fused BN2 column stats.
    // Pipeline smem is dead after the last compute; one barrier protects it.
    if (MODE == 1) __syncthreads();

    #pragma unroll
    for (int mt = 0; mt < 4; mt++) {
        int r0 = m0 + wm * 64 + mt * 16 + g;
        int r1 = r0 + 8;
        #pragma unroll
        for (int nt = 0; nt < 8; nt++) {
            int cb = n0 + wn * 64 + nt * 8 + tg * 2;
            float* c = acc[mt][nt];
            float2 bi = *(const float2*)&bias[cb];
            if (MODE == 0) {
                __half2 h0 = __floats2half2_rn(gelu_exact(c[0] + bi.x),
                                               gelu_exact(c[1] + bi.y));
                __half2 h1 = __floats2half2_rn(gelu_exact(c[2] + bi.x),
                                               gelu_exact(c[3] + bi.y));
                *(__half2*)&outh[(size_t)r0 * OSTR + cb] = h0;
                *(__half2*)&outh[(size_t)r1 * OSTR + cb] = h1;
            } else if (MODE == 1) {
                float2 al = *(const float2*)&g_al[cb];
                float2 bt = *(const float2*)&g_bt[cb];
                float2 s0 = *(const float2*)&src[(size_t)r0 * DM + cb];
                float2 s1 = *(const float2*)&src[(size_t)r1 * DM + cb];
                float2 o0 = make_float2(c[0] + bi.x + s0.x * al.x + bt.x,
                                        c[1] + bi.y + s0.y * al.y + bt.y);
                float2 o1 = make_float2(c[2] + bi.x + s1.x * al.x + bt.x,
                                        c[3] + bi.y + s1.y * al.y + bt.y);
                *(float2*)&outf[(size_t)r0 * OSTR + cb] = o0;
                *(float2*)&outf[(size_t)r1 * OSTR + cb] = o1;
                int rl0 = wm * 64 + mt * 16 + g;      // local rows
                int cl  = wn * 64 + nt * 8 + tg * 2;  // local cols
                *(__half2*)&dynh[rl0 * 128 + cl]       = __floats2half2_rn(o0.x, o0.y);
                *(__half2*)&dynh[(rl0 + 8) * 128 + cl] = __floats2half2_rn(o1.x, o1.y);
            } else {
                int cl = cb - ncorr;
                float2 o0 = make_float2(c[0] + bi.x, c[1] + bi.y);
                float2 o1 = make_float2(c[2] + bi.x, c[3] + bi.y);
                *(float2*)&outfp[(size_t)r0 * OSTR + cl] = o0;
                *(float2*)&outfp[(size_t)r1 * OSTR + cl] = o1;
            }
        }
    }

    if (MODE == 1) {
        __syncthreads();
        // each thread reduces one column of the 128x128 staged tile
        float s = 0.0f, q = 0.0f;
        #pragma unroll 8
        for (int r = 0; r < 128; r++) {
            float v = __half2float(dynh[r * 128 + tid]);
            s += v; q += v * v;
        }
        g_psum[(size_t)(n0 + tid) * NSTATB + blockIdx.y] = s;
        g_psq [(size_t)(n0 + tid) * NSTATB + blockIdx.y] = q;
    }
}

// ---------------------------------------------------------------- launch
extern "C" void kernel_launch(void* const* d_in, const int* in_sizes, int n_in,
                              void* d_out, int out_size)
{
    const float* x_re   = (const float*)d_in[0];
    const float* x_im   = (const float*)d_in[1];
    const float* embWre = (const float*)d_in[2];
    const float* embWim = (const float*)d_in[3];
    const float* embbre = (const float*)d_in[4];
    const float* embbim = (const float*)d_in[5];
    const float* W1     = (const float*)d_in[6];
    const float* b1     = (const float*)d_in[7];
    const float* W2     = (const float*)d_in[8];
    const float* b2     = (const float*)d_in[9];
    const float* gamma1 = (const float*)d_in[10];
    const float* beta1  = (const float*)d_in[11];
    const float* gamma2 = (const float*)d_in[12];
    const float* beta2  = (const float*)d_in[13];
    float* out = (float*)d_out;

    float*  act  = nullptr; float*  src = nullptr; __half* srch = nullptr;
    __half* ffh  = nullptr; float*  P   = nullptr;
    __half* w1h  = nullptr; float*  b1m = nullptr; __half* w2h  = nullptr;
    __half* wEh  = nullptr; float*  bE  = nullptr;
    cudaGetSymbolAddress((void**)&act,  g_act);
    cudaGetSymbolAddress((void**)&src,  g_src);
    cudaGetSymbolAddress((void**)&srch, g_srch);
    cudaGetSymbolAddress((void**)&ffh,  g_ffh);
    cudaGetSymbolAddress((void**)&P,    g_P);
    cudaGetSymbolAddress((void**)&w1h,  g_w1h);
    cudaGetSymbolAddress((void**)&b1m,  g_b1m);
    cudaGetSymbolAddress((void**)&w2h,  g_w2h);
    cudaGetSymbolAddress((void**)&wEh,  g_wEh);
    cudaGetSymbolAddress((void**)&bE,   g_bE);

    cudaFuncSetAttribute(k_ffgemm<0>, cudaFuncAttributeMaxDynamicSharedMemorySize, DYNSM);
    cudaFuncSetAttribute(k_ffgemm<1>, cudaFuncAttributeMaxDynamicSharedMemorySize, DYNSM);
    cudaFuncSetAttribute(k_ffgemm<2>, cudaFuncAttributeMaxDynamicSharedMemorySize, DYNSM);

    k_init_affine<<<1, DM>>>();
    k_roundW2<<<(NL * DM * DFF) / 256, 256>>>(W2);

    // embed: pack fp16 operands, then fp16 GEMM
    __half* Ah = (__half*)P;   // reuse g_P (embed runs before any attn)
    {
        size_t na = (size_t)EMB_M * KEMB;
        k_packA<<<(int)((na + 255) / 256), 256>>>(x_re, x_im, Ah);
        size_t nb = (size_t)512 * KEMB;
        k_packW<<<(int)((nb + 255) / 256), 256>>>(embWre, embWim);
        k_packBias<<<1, 512>>>(embbre, embbim);
        dim3 ge(512 / 128, EMB_M / 128);
        k_ffgemm<2><<<ge, 128, DYNSM>>>(Ah, wEh, bE, nullptr, act, nullptr);
    }

    for (int l = 0; l < NL; l++) {
        const float* W1l = W1 + (size_t)l * DFF * DM;
        const float* b1l = b1 + (size_t)l * DFF;
        const float* b2l = b2 + (size_t)l * DM;
        __half* w2hl = w2h + (size_t)l * DM * DFF;

        {
            dim3 ga((CC + 31) / 32, DM / 32, BB);
            k_attn<<<ga, 256>>>(act, src, srch);
        }

        k_stats_h<<<NSTATB, DM>>>(srch);
        k_finalize<<<DM, 256>>>(gamma1 + l * DM, beta1 + l * DM);
        k_fold<<<DFF, DM>>>(W1l, b1l);

        {
            dim3 g1(DFF / 128, MROWS / 128);
            k_ffgemm<0><<<g1, 128, DYNSM>>>(srch, w1h, b1m, nullptr, nullptr, ffh);
            dim3 g2(DM / 128, MROWS / 128);
            k_ffgemm<1><<<g2, 128, DYNSM>>>(ffh, w2hl, b2l, src, act, nullptr);
        }

        // BN2 stats produced by ff2's fused smem-staged epilogue
        k_finalize<<<DM, 256>>>(gamma2 + l * DM, beta2 + l * DM);
    }

    const size_t NO = (size_t)BB * CC * DM;
    k_out<<<(int)((NO + 255) / 256), 256>>>(act, out);
}